// round 15
// baseline (speedup 1.0000x reference)
#include <cuda_runtime.h>
#include <cuda_fp16.h>
#include <cstdint>

#define N_NODES 50000
#define N_EDGES 800000
#define D 96
#define SCAN_TILE 1024
#define NB ((N_NODES + SCAN_TILE - 1) / SCAN_TILE)   // 49

typedef unsigned long long ull;
typedef unsigned int uint32;

// ---------------- device scratch (no allocations allowed) -------------------
__device__ int g_cnt[N_NODES];       // per-dst degree (histogram)
__device__ int g_rowptr[N_NODES];    // block-LOCAL exclusive scan of degrees
__device__ int g_pos[N_NODES];       // scatter cursors (block-local base)
__device__ int g_bsum[NB];           // per-scan-block totals
__device__ int g_bsumx[NB];          // exclusive scan of block totals
__device__ int g_csr_src[N_EDGES];   // src node per CSR slot
__device__ int g_scan_tick;          // block-completion counter (static 0)
__device__ __half g_xh[(size_t)N_NODES * D];  // fp16 shadow of x (gather feed)

// true rowptr[i] = g_rowptr[i] + g_bsumx[i >> 10]

// ---------------------------------------------------------------------------
// K1: FUSED x->fp16 convert + dst-degree histogram.
//     Threads [0, 600000): convert 8 floats each.
//     Threads [600000, 800000): histogram 4 edges each (RED atomics).
// ---------------------------------------------------------------------------
#define CVT_T (N_NODES * D / 8)        // 600,000
#define HIST_T (N_EDGES / 4)           // 200,000

__global__ void k_cvt_hist(const float4* __restrict__ x4,
                           const int* __restrict__ ei) {
    int tid = blockIdx.x * blockDim.x + threadIdx.x;
    if (tid < CVT_T) {
        float4 a = x4[2 * tid];
        float4 b = x4[2 * tid + 1];
        __half2 h0 = __float22half2_rn(make_float2(a.x, a.y));
        __half2 h1 = __float22half2_rn(make_float2(a.z, a.w));
        __half2 h2 = __float22half2_rn(make_float2(b.x, b.y));
        __half2 h3 = __float22half2_rn(make_float2(b.z, b.w));
        uint4 o;
        o.x = *reinterpret_cast<uint32*>(&h0);
        o.y = *reinterpret_cast<uint32*>(&h1);
        o.z = *reinterpret_cast<uint32*>(&h2);
        o.w = *reinterpret_cast<uint32*>(&h3);
        reinterpret_cast<uint4*>(g_xh)[tid] = o;
    } else {
        int i = tid - CVT_T;
        if (i < HIST_T) {
            int4 d4 = *reinterpret_cast<const int4*>(ei + N_EDGES + i * 4);
            atomicAdd(&g_cnt[d4.x], 1);
            atomicAdd(&g_cnt[d4.y], 1);
            atomicAdd(&g_cnt[d4.z], 1);
            atomicAdd(&g_cnt[d4.w], 1);
        }
    }
}

// ---------------------------------------------------------------------------
// K2: per-block local exclusive scan; LAST block scans the 49 block totals.
// ---------------------------------------------------------------------------
__global__ __launch_bounds__(256) void k_scan1() {
    __shared__ int wsum[8];
    __shared__ bool is_last;
    const int blk = blockIdx.x, t = threadIdx.x;
    const int lane = t & 31, wid = t >> 5;
    int idx = blk * SCAN_TILE + t * 4;
    int v[4];
    #pragma unroll
    for (int i = 0; i < 4; i++)
        v[i] = (idx + i < N_NODES) ? g_cnt[idx + i] : 0;
    int tsum = v[0] + v[1] + v[2] + v[3];

    int incl = tsum;
    #pragma unroll
    for (int off = 1; off < 32; off <<= 1) {
        int s = __shfl_up_sync(0xffffffffu, incl, off);
        if (lane >= off) incl += s;
    }
    if (lane == 31) wsum[wid] = incl;
    __syncthreads();
    if (t == 0) {
        int s = 0;
        #pragma unroll
        for (int i = 0; i < 8; i++) { int x = wsum[i]; wsum[i] = s; s += x; }
        g_bsum[blk] = s;
    }
    __syncthreads();
    int excl = wsum[wid] + (incl - tsum);
    #pragma unroll
    for (int i = 0; i < 4; i++) {
        if (idx + i < N_NODES) {
            g_rowptr[idx + i] = excl;
            g_pos[idx + i]    = excl;
        }
        excl += v[i];
    }

    __threadfence();
    if (t == 0) is_last = (atomicAdd(&g_scan_tick, 1) == NB - 1);
    __syncthreads();
    if (is_last && t == 0) {
        const volatile int* bs = g_bsum;
        int a = 0;
        #pragma unroll
        for (int i = 0; i < NB; i++) { int x = bs[i]; g_bsumx[i] = a; a += x; }
        g_scan_tick = 0;
        __threadfence();
    }
}

// ---------------------------------------------------------------------------
// K3: scatter src ids, 4 edges/thread (4 independent atomic->store chains).
// ---------------------------------------------------------------------------
__global__ void k_scatter(const int* __restrict__ ei) {
    int i = blockIdx.x * blockDim.x + threadIdx.x;
    int e = i * 4;
    if (e >= N_EDGES) return;
    int4 s4 = *reinterpret_cast<const int4*>(ei + e);
    int4 d4 = *reinterpret_cast<const int4*>(ei + N_EDGES + e);
    int p0 = atomicAdd(&g_pos[d4.x], 1);
    int p1 = atomicAdd(&g_pos[d4.y], 1);
    int p2 = atomicAdd(&g_pos[d4.z], 1);
    int p3 = atomicAdd(&g_pos[d4.w], 1);
    g_csr_src[p0 + g_bsumx[d4.x >> 10]] = s4.x;
    g_csr_src[p1 + g_bsumx[d4.y >> 10]] = s4.y;
    g_csr_src[p2 + g_bsumx[d4.z >> 10]] = s4.z;
    g_csr_src[p3 + g_bsumx[d4.w >> 10]] = s4.w;
}

// ---------------------------------------------------------------------------
// K4: warp-per-node mean aggregation from fp16 shadow. Lanes 0..23 own
//     4 halves (8B) at col=lane*4; fp32 accumulation; unroll 4 neighbors.
// ---------------------------------------------------------------------------
__device__ __forceinline__ void acc_half4(float acc[4], uint2 v) {
    __half2 h0 = *reinterpret_cast<__half2*>(&v.x);
    __half2 h1 = *reinterpret_cast<__half2*>(&v.y);
    float2 f0 = __half22float2(h0);
    float2 f1 = __half22float2(h1);
    acc[0] += f0.x; acc[1] += f0.y; acc[2] += f1.x; acc[3] += f1.y;
}

__global__ void k_agg(float* __restrict__ out) {
    int gw = (blockIdx.x * blockDim.x + threadIdx.x) >> 5;
    if (gw >= N_NODES) return;
    int lane = threadIdx.x & 31;
    int beg = g_rowptr[gw] + g_bsumx[gw >> 10];
    int end = (gw + 1 < N_NODES)
            ? (g_rowptr[gw + 1] + g_bsumx[(gw + 1) >> 10]) : N_EDGES;

    const bool act = lane < 24;
    const int col = lane * 4;
    const __half* xh = g_xh;

    float a[4] = {0.f, 0.f, 0.f, 0.f};
    float b[4] = {0.f, 0.f, 0.f, 0.f};

    int j = beg;
    for (; j + 4 <= end; j += 4) {
        int s0 = __ldg(g_csr_src + j + 0);
        int s1 = __ldg(g_csr_src + j + 1);
        int s2 = __ldg(g_csr_src + j + 2);
        int s3 = __ldg(g_csr_src + j + 3);
        if (act) {
            uint2 v0 = *reinterpret_cast<const uint2*>(xh + (size_t)s0 * D + col);
            uint2 v1 = *reinterpret_cast<const uint2*>(xh + (size_t)s1 * D + col);
            uint2 v2 = *reinterpret_cast<const uint2*>(xh + (size_t)s2 * D + col);
            uint2 v3 = *reinterpret_cast<const uint2*>(xh + (size_t)s3 * D + col);
            acc_half4(a, v0);
            acc_half4(b, v1);
            acc_half4(a, v2);
            acc_half4(b, v3);
        }
    }
    for (; j < end; j++) {
        int s = __ldg(g_csr_src + j);
        if (act) {
            uint2 v = *reinterpret_cast<const uint2*>(xh + (size_t)s * D + col);
            acc_half4(a, v);
        }
    }
    #pragma unroll
    for (int q = 0; q < 4; q++) a[q] += b[q];

    int deg = end - beg;
    float inv = (deg > 0) ? 1.0f / (float)deg : 0.0f;
    if (act) {
        float4 r = make_float4(a[0] * inv, a[1] * inv, a[2] * inv, a[3] * inv);
        *reinterpret_cast<float4*>(out + (size_t)gw * D + col) = r;
    }
}

// ---------------------------------------------------------------------------
// K5: tf32 tensor-core linear + ReLU (unchanged, R13-proven).
// ---------------------------------------------------------------------------
constexpr int APAD = 100;
constexpr int LTHREADS = 128;
constexpr int SMEM_FLOATS = 128 * APAD + 96 * APAD + 96;
constexpr size_t SMEM_BYTES = (size_t)SMEM_FLOATS * sizeof(float);  // 89,984 B

__device__ __forceinline__ uint32 to_tf32(float f) {
    uint32 u;
    asm("cvt.rna.tf32.f32 %0, %1;" : "=r"(u) : "f"(f));
    return u;
}
__device__ __forceinline__ void mma_tf32(float c[4], const uint32 a[4],
                                         const uint32 b[2]) {
    asm("mma.sync.aligned.m16n8k8.row.col.f32.tf32.tf32.f32 "
        "{%0,%1,%2,%3}, {%4,%5,%6,%7}, {%8,%9}, {%0,%1,%2,%3};"
        : "+f"(c[0]), "+f"(c[1]), "+f"(c[2]), "+f"(c[3])
        : "r"(a[0]), "r"(a[1]), "r"(a[2]), "r"(a[3]), "r"(b[0]), "r"(b[1]));
}

__global__ __launch_bounds__(LTHREADS, 2)
void k_linear(const float* __restrict__ x,
              const float* __restrict__ Wl,
              const float* __restrict__ bl,
              const float* __restrict__ Wr,
              float* __restrict__ out)   // agg_mean on entry, z on exit
{
    extern __shared__ float smem[];
    float* As  = smem;                  // [128][APAD] tf32 bits
    float* Ws  = smem + 128 * APAD;     // [96][APAD]  tf32 bits
    float* bls = Ws + 96 * APAD;        // [96]

    const int t = threadIdx.x;
    const int warp = t >> 5, lane = t & 31;
    const int g = lane >> 2, tq = lane & 3;
    const int rowBase = blockIdx.x * 128;
    if (t < 96) bls[t] = bl[t];

    float c[2][12][4];
    #pragma unroll
    for (int m = 0; m < 2; m++)
        #pragma unroll
        for (int n = 0; n < 12; n++)
            #pragma unroll
            for (int q = 0; q < 4; q++) c[m][n][q] = 0.f;

    #pragma unroll
    for (int h = 0; h < 2; h++) {
        const float* W   = h ? Wr : Wl;
        const float* src = h ? x  : out;

        for (int idx = t; idx < D * D; idx += LTHREADS) {
            int o = idx / D, k = idx - o * D;
            *reinterpret_cast<uint32*>(Ws + o * APAD + k) = to_tf32(W[idx]);
        }
        for (int idx = t; idx < 128 * (D / 4); idx += LTHREADS) {
            int r = idx / (D / 4), q = idx - r * (D / 4);
            int node = rowBase + r;
            float4 v = make_float4(0.f, 0.f, 0.f, 0.f);
            if (node < N_NODES)
                v = *reinterpret_cast<const float4*>(src + (size_t)node * D + q * 4);
            uint32* dst = reinterpret_cast<uint32*>(As + r * APAD + q * 4);
            dst[0] = to_tf32(v.x); dst[1] = to_tf32(v.y);
            dst[2] = to_tf32(v.z); dst[3] = to_tf32(v.w);
        }
        __syncthreads();

        for (int kt = 0; kt < 12; kt++) {
            const int kb = kt * 8;
            uint32 a[2][4];
            #pragma unroll
            for (int m = 0; m < 2; m++) {
                const uint32* ap = reinterpret_cast<const uint32*>(
                    As + (warp * 32 + m * 16) * APAD + kb);
                a[m][0] = ap[(g)     * APAD + tq];
                a[m][1] = ap[(g + 8) * APAD + tq];
                a[m][2] = ap[(g)     * APAD + tq + 4];
                a[m][3] = ap[(g + 8) * APAD + tq + 4];
            }
            uint32 b[12][2];
            #pragma unroll
            for (int n = 0; n < 12; n++) {
                const uint32* bp = reinterpret_cast<const uint32*>(
                    Ws + (n * 8 + g) * APAD + kb);
                b[n][0] = bp[tq];
                b[n][1] = bp[tq + 4];
            }
            #pragma unroll
            for (int m = 0; m < 2; m++)
                #pragma unroll
                for (int n = 0; n < 12; n++)
                    mma_tf32(c[m][n], a[m], b[n]);
        }
        __syncthreads();
    }

    #pragma unroll
    for (int m = 0; m < 2; m++) {
        int row0 = rowBase + warp * 32 + m * 16 + g;
        int row1 = row0 + 8;
        #pragma unroll
        for (int n = 0; n < 12; n++) {
            int col = n * 8 + tq * 2;
            float bb0 = bls[col], bb1 = bls[col + 1];
            if (row0 < N_NODES) {
                float2 r0 = make_float2(fmaxf(c[m][n][0] + bb0, 0.f),
                                        fmaxf(c[m][n][1] + bb1, 0.f));
                *reinterpret_cast<float2*>(out + (size_t)row0 * D + col) = r0;
            }
            if (row1 < N_NODES) {
                float2 r1 = make_float2(fmaxf(c[m][n][2] + bb0, 0.f),
                                        fmaxf(c[m][n][3] + bb1, 0.f));
                *reinterpret_cast<float2*>(out + (size_t)row1 * D + col) = r1;
            }
        }
    }
}

// ---------------------------------------------------------------------------
extern "C" void kernel_launch(void* const* d_in, const int* in_sizes, int n_in,
                              void* d_out, int out_size) {
    const float* x  = (const float*)d_in[0];   // [N, 96]
    const int* ei   = (const int*)d_in[1];     // [2, E]
    const float* Wl = (const float*)d_in[2];   // [96, 96]
    const float* bl = (const float*)d_in[3];   // [96]
    const float* Wr = (const float*)d_in[4];   // [96, 96]
    float* out = (float*)d_out;                // [N, 96]

    cudaFuncSetAttribute(k_linear, cudaFuncAttributeMaxDynamicSharedMemorySize,
                         (int)SMEM_BYTES);

    void* cnt_ptr = nullptr;
    cudaGetSymbolAddress(&cnt_ptr, g_cnt);
    cudaMemsetAsync(cnt_ptr, 0, sizeof(int) * N_NODES);

    k_cvt_hist<<<(CVT_T + HIST_T + 255) / 256, 256>>>((const float4*)x, ei);
    k_scan1<<<NB, 256>>>();
    k_scatter<<<(N_EDGES / 4 + 255) / 256, 256>>>(ei);
    {
        int warps_per_block = 8;
        int blocks = (N_NODES + warps_per_block - 1) / warps_per_block;
        k_agg<<<blocks, warps_per_block * 32>>>(out);
    }
    k_linear<<<(N_NODES + 127) / 128, LTHREADS, SMEM_BYTES>>>(x, Wl, bl, Wr, out);
}

// round 16
// speedup vs baseline: 1.0694x; 1.0694x over previous
#include <cuda_runtime.h>
#include <cuda_fp16.h>
#include <cstdint>

#define N_NODES 50000
#define N_EDGES 800000
#define D 96
#define SCAN_TILE 1024
#define NB ((N_NODES + SCAN_TILE - 1) / SCAN_TILE)   // 49

typedef unsigned long long ull;
typedef unsigned int uint32;

// ---------------- device scratch (no allocations allowed) -------------------
__device__ int g_cnt[N_NODES];       // per-dst degree (histogram)
__device__ int g_rowptr[N_NODES];    // block-LOCAL exclusive scan of degrees
__device__ int g_bsum[NB];           // per-scan-block totals
__device__ int g_bsumx[NB];          // exclusive scan of block totals
__device__ int g_rank[N_EDGES];      // within-dst rank (from hist atomics)
__device__ int g_csr_src[N_EDGES];   // src node per CSR slot
__device__ int g_scan_tick;          // block-completion counter (static 0)
__device__ __half g_xh[(size_t)N_NODES * D];  // fp16 shadow of x

// true rowptr[i] = g_rowptr[i] + g_bsumx[i >> 10]

// ---------------------------------------------------------------------------
// K1: FUSED x->fp16 convert + dst-degree histogram (rank recorded).
//     Threads [0, 600000): convert 8 floats each.
//     Threads [600000, 800000): 4 edges each; rank = atomicAdd return.
// ---------------------------------------------------------------------------
#define CVT_T (N_NODES * D / 8)        // 600,000
#define HIST_T (N_EDGES / 4)           // 200,000

__global__ void k_cvt_hist(const float4* __restrict__ x4,
                           const int* __restrict__ ei) {
    int tid = blockIdx.x * blockDim.x + threadIdx.x;
    if (tid < CVT_T) {
        float4 a = x4[2 * tid];
        float4 b = x4[2 * tid + 1];
        __half2 h0 = __float22half2_rn(make_float2(a.x, a.y));
        __half2 h1 = __float22half2_rn(make_float2(a.z, a.w));
        __half2 h2 = __float22half2_rn(make_float2(b.x, b.y));
        __half2 h3 = __float22half2_rn(make_float2(b.z, b.w));
        uint4 o;
        o.x = *reinterpret_cast<uint32*>(&h0);
        o.y = *reinterpret_cast<uint32*>(&h1);
        o.z = *reinterpret_cast<uint32*>(&h2);
        o.w = *reinterpret_cast<uint32*>(&h3);
        reinterpret_cast<uint4*>(g_xh)[tid] = o;
    } else {
        int i = tid - CVT_T;
        if (i < HIST_T) {
            int4 d4 = *reinterpret_cast<const int4*>(ei + N_EDGES + i * 4);
            int4 r;
            r.x = atomicAdd(&g_cnt[d4.x], 1);
            r.y = atomicAdd(&g_cnt[d4.y], 1);
            r.z = atomicAdd(&g_cnt[d4.z], 1);
            r.w = atomicAdd(&g_cnt[d4.w], 1);
            *reinterpret_cast<int4*>(g_rank + i * 4) = r;   // coalesced
        }
    }
}

// ---------------------------------------------------------------------------
// K2: per-block local exclusive scan; LAST block scans the 49 block totals.
// ---------------------------------------------------------------------------
__global__ __launch_bounds__(256) void k_scan1() {
    __shared__ int wsum[8];
    __shared__ bool is_last;
    const int blk = blockIdx.x, t = threadIdx.x;
    const int lane = t & 31, wid = t >> 5;
    int idx = blk * SCAN_TILE + t * 4;
    int v[4];
    #pragma unroll
    for (int i = 0; i < 4; i++)
        v[i] = (idx + i < N_NODES) ? g_cnt[idx + i] : 0;
    int tsum = v[0] + v[1] + v[2] + v[3];

    int incl = tsum;
    #pragma unroll
    for (int off = 1; off < 32; off <<= 1) {
        int s = __shfl_up_sync(0xffffffffu, incl, off);
        if (lane >= off) incl += s;
    }
    if (lane == 31) wsum[wid] = incl;
    __syncthreads();
    if (t == 0) {
        int s = 0;
        #pragma unroll
        for (int i = 0; i < 8; i++) { int x = wsum[i]; wsum[i] = s; s += x; }
        g_bsum[blk] = s;
    }
    __syncthreads();
    int excl = wsum[wid] + (incl - tsum);
    #pragma unroll
    for (int i = 0; i < 4; i++) {
        if (idx + i < N_NODES) g_rowptr[idx + i] = excl;
        excl += v[i];
    }

    __threadfence();
    if (t == 0) is_last = (atomicAdd(&g_scan_tick, 1) == NB - 1);
    __syncthreads();
    if (is_last && t == 0) {
        const volatile int* bs = g_bsum;
        int a = 0;
        #pragma unroll
        for (int i = 0; i < NB; i++) { int x = bs[i]; g_bsumx[i] = a; a += x; }
        g_scan_tick = 0;
        __threadfence();
    }
}

// ---------------------------------------------------------------------------
// K3: atomic-free scatter: slot = rowptr[dst] + bsumx[dst>>10] + rank[e]
// ---------------------------------------------------------------------------
__global__ void k_scatter(const int* __restrict__ ei) {
    int e = blockIdx.x * blockDim.x + threadIdx.x;
    if (e >= N_EDGES) return;
    int dst = ei[N_EDGES + e];
    int p = g_rowptr[dst] + g_bsumx[dst >> 10] + g_rank[e];
    g_csr_src[p] = ei[e];
}

// ---------------------------------------------------------------------------
// K4: warp-per-node mean aggregation from fp16 shadow.
//     Lanes 0..23 own 4 halves (8B). Batches of 4 neighbors are summed in
//     packed fp16 (HADD2 tree, 3 adds), then flushed to fp32 accumulators.
// ---------------------------------------------------------------------------
__device__ __forceinline__ uint32 hadd2(uint32 a, uint32 b) {
    uint32 r;
    asm("add.rn.f16x2 %0, %1, %2;" : "=r"(r) : "r"(a), "r"(b));
    return r;
}

__global__ void k_agg(float* __restrict__ out) {
    int gw = (blockIdx.x * blockDim.x + threadIdx.x) >> 5;
    if (gw >= N_NODES) return;
    int lane = threadIdx.x & 31;
    int beg = g_rowptr[gw] + g_bsumx[gw >> 10];
    int end = (gw + 1 < N_NODES)
            ? (g_rowptr[gw + 1] + g_bsumx[(gw + 1) >> 10]) : N_EDGES;

    const bool act = lane < 24;
    const int col = lane * 4;
    const __half* xh = g_xh;

    float a0 = 0.f, a1 = 0.f, a2 = 0.f, a3 = 0.f;

    int j = beg;
    for (; j + 4 <= end; j += 4) {
        int s0 = __ldg(g_csr_src + j + 0);
        int s1 = __ldg(g_csr_src + j + 1);
        int s2 = __ldg(g_csr_src + j + 2);
        int s3 = __ldg(g_csr_src + j + 3);
        if (act) {
            uint2 v0 = *reinterpret_cast<const uint2*>(xh + (size_t)s0 * D + col);
            uint2 v1 = *reinterpret_cast<const uint2*>(xh + (size_t)s1 * D + col);
            uint2 v2 = *reinterpret_cast<const uint2*>(xh + (size_t)s2 * D + col);
            uint2 v3 = *reinterpret_cast<const uint2*>(xh + (size_t)s3 * D + col);
            // fp16 tree-sum of 4 neighbors (2 independent pairs, then join)
            uint32 lo = hadd2(hadd2(v0.x, v1.x), hadd2(v2.x, v3.x));
            uint32 hi = hadd2(hadd2(v0.y, v1.y), hadd2(v2.y, v3.y));
            float2 flo = __half22float2(*reinterpret_cast<__half2*>(&lo));
            float2 fhi = __half22float2(*reinterpret_cast<__half2*>(&hi));
            a0 += flo.x; a1 += flo.y; a2 += fhi.x; a3 += fhi.y;
        }
    }
    for (; j < end; j++) {
        int s = __ldg(g_csr_src + j);
        if (act) {
            uint2 v = *reinterpret_cast<const uint2*>(xh + (size_t)s * D + col);
            float2 flo = __half22float2(*reinterpret_cast<__half2*>(&v.x));
            float2 fhi = __half22float2(*reinterpret_cast<__half2*>(&v.y));
            a0 += flo.x; a1 += flo.y; a2 += fhi.x; a3 += fhi.y;
        }
    }

    int deg = end - beg;
    float inv = (deg > 0) ? 1.0f / (float)deg : 0.0f;
    if (act) {
        float4 r = make_float4(a0 * inv, a1 * inv, a2 * inv, a3 * inv);
        *reinterpret_cast<float4*>(out + (size_t)gw * D + col) = r;
    }
}

// ---------------------------------------------------------------------------
// K5: tf32 tensor-core linear + ReLU (unchanged, R13-proven).
// ---------------------------------------------------------------------------
constexpr int APAD = 100;
constexpr int LTHREADS = 128;
constexpr int SMEM_FLOATS = 128 * APAD + 96 * APAD + 96;
constexpr size_t SMEM_BYTES = (size_t)SMEM_FLOATS * sizeof(float);  // 89,984 B

__device__ __forceinline__ uint32 to_tf32(float f) {
    uint32 u;
    asm("cvt.rna.tf32.f32 %0, %1;" : "=r"(u) : "f"(f));
    return u;
}
__device__ __forceinline__ void mma_tf32(float c[4], const uint32 a[4],
                                         const uint32 b[2]) {
    asm("mma.sync.aligned.m16n8k8.row.col.f32.tf32.tf32.f32 "
        "{%0,%1,%2,%3}, {%4,%5,%6,%7}, {%8,%9}, {%0,%1,%2,%3};"
        : "+f"(c[0]), "+f"(c[1]), "+f"(c[2]), "+f"(c[3])
        : "r"(a[0]), "r"(a[1]), "r"(a[2]), "r"(a[3]), "r"(b[0]), "r"(b[1]));
}

__global__ __launch_bounds__(LTHREADS, 2)
void k_linear(const float* __restrict__ x,
              const float* __restrict__ Wl,
              const float* __restrict__ bl,
              const float* __restrict__ Wr,
              float* __restrict__ out)   // agg_mean on entry, z on exit
{
    extern __shared__ float smem[];
    float* As  = smem;                  // [128][APAD] tf32 bits
    float* Ws  = smem + 128 * APAD;     // [96][APAD]  tf32 bits
    float* bls = Ws + 96 * APAD;        // [96]

    const int t = threadIdx.x;
    const int warp = t >> 5, lane = t & 31;
    const int g = lane >> 2, tq = lane & 3;
    const int rowBase = blockIdx.x * 128;
    if (t < 96) bls[t] = bl[t];

    float c[2][12][4];
    #pragma unroll
    for (int m = 0; m < 2; m++)
        #pragma unroll
        for (int n = 0; n < 12; n++)
            #pragma unroll
            for (int q = 0; q < 4; q++) c[m][n][q] = 0.f;

    #pragma unroll
    for (int h = 0; h < 2; h++) {
        const float* W   = h ? Wr : Wl;
        const float* src = h ? x  : out;

        for (int idx = t; idx < D * D; idx += LTHREADS) {
            int o = idx / D, k = idx - o * D;
            *reinterpret_cast<uint32*>(Ws + o * APAD + k) = to_tf32(W[idx]);
        }
        for (int idx = t; idx < 128 * (D / 4); idx += LTHREADS) {
            int r = idx / (D / 4), q = idx - r * (D / 4);
            int node = rowBase + r;
            float4 v = make_float4(0.f, 0.f, 0.f, 0.f);
            if (node < N_NODES)
                v = *reinterpret_cast<const float4*>(src + (size_t)node * D + q * 4);
            uint32* dst = reinterpret_cast<uint32*>(As + r * APAD + q * 4);
            dst[0] = to_tf32(v.x); dst[1] = to_tf32(v.y);
            dst[2] = to_tf32(v.z); dst[3] = to_tf32(v.w);
        }
        __syncthreads();

        for (int kt = 0; kt < 12; kt++) {
            const int kb = kt * 8;
            uint32 a[2][4];
            #pragma unroll
            for (int m = 0; m < 2; m++) {
                const uint32* ap = reinterpret_cast<const uint32*>(
                    As + (warp * 32 + m * 16) * APAD + kb);
                a[m][0] = ap[(g)     * APAD + tq];
                a[m][1] = ap[(g + 8) * APAD + tq];
                a[m][2] = ap[(g)     * APAD + tq + 4];
                a[m][3] = ap[(g + 8) * APAD + tq + 4];
            }
            uint32 b[12][2];
            #pragma unroll
            for (int n = 0; n < 12; n++) {
                const uint32* bp = reinterpret_cast<const uint32*>(
                    Ws + (n * 8 + g) * APAD + kb);
                b[n][0] = bp[tq];
                b[n][1] = bp[tq + 4];
            }
            #pragma unroll
            for (int m = 0; m < 2; m++)
                #pragma unroll
                for (int n = 0; n < 12; n++)
                    mma_tf32(c[m][n], a[m], b[n]);
        }
        __syncthreads();
    }

    #pragma unroll
    for (int m = 0; m < 2; m++) {
        int row0 = rowBase + warp * 32 + m * 16 + g;
        int row1 = row0 + 8;
        #pragma unroll
        for (int n = 0; n < 12; n++) {
            int col = n * 8 + tq * 2;
            float bb0 = bls[col], bb1 = bls[col + 1];
            if (row0 < N_NODES) {
                float2 r0 = make_float2(fmaxf(c[m][n][0] + bb0, 0.f),
                                        fmaxf(c[m][n][1] + bb1, 0.f));
                *reinterpret_cast<float2*>(out + (size_t)row0 * D + col) = r0;
            }
            if (row1 < N_NODES) {
                float2 r1 = make_float2(fmaxf(c[m][n][2] + bb0, 0.f),
                                        fmaxf(c[m][n][3] + bb1, 0.f));
                *reinterpret_cast<float2*>(out + (size_t)row1 * D + col) = r1;
            }
        }
    }
}

// ---------------------------------------------------------------------------
extern "C" void kernel_launch(void* const* d_in, const int* in_sizes, int n_in,
                              void* d_out, int out_size) {
    const float* x  = (const float*)d_in[0];   // [N, 96]
    const int* ei   = (const int*)d_in[1];     // [2, E]
    const float* Wl = (const float*)d_in[2];   // [96, 96]
    const float* bl = (const float*)d_in[3];   // [96]
    const float* Wr = (const float*)d_in[4];   // [96, 96]
    float* out = (float*)d_out;                // [N, 96]

    cudaFuncSetAttribute(k_linear, cudaFuncAttributeMaxDynamicSharedMemorySize,
                         (int)SMEM_BYTES);

    void* cnt_ptr = nullptr;
    cudaGetSymbolAddress(&cnt_ptr, g_cnt);
    cudaMemsetAsync(cnt_ptr, 0, sizeof(int) * N_NODES);

    k_cvt_hist<<<(CVT_T + HIST_T + 255) / 256, 256>>>((const float4*)x, ei);
    k_scan1<<<NB, 256>>>();
    k_scatter<<<(N_EDGES + 255) / 256, 256>>>(ei);
    {
        int warps_per_block = 8;
        int blocks = (N_NODES + warps_per_block - 1) / warps_per_block;
        k_agg<<<blocks, warps_per_block * 32>>>(out);
    }
    k_linear<<<(N_NODES + 127) / 128, LTHREADS, SMEM_BYTES>>>(x, Wl, bl, Wr, out);
}